// round 4
// baseline (speedup 1.0000x reference)
#include <cuda_runtime.h>

#define N_SEG   65536
#define TOTAL   2097152
#define D       128
#define THREADS 128
#define GRID    2432   /* 152 SMs x 16 CTAs; work stealing tolerates mismatch */

// 1 -> indptr is int32, 0 -> indptr is int64
__device__ int g_indptr_is32;
__device__ unsigned int g_work;

__global__ void init_kernel(const int* __restrict__ indptr32) {
    // Safe probe: word 65536 exists in both layouts.
    // int32 layout: indptr32[65536] == TOTAL (last element).
    // int64 layout: indptr32[65536] == high word of indptr[32768] == 0.
    g_indptr_is32 = (indptr32[N_SEG] == TOTAL) ? 1 : 0;
    g_work = 0u;
}

__device__ __forceinline__ void acc4(float4& a, const float4 v) {
    a.x += v.x; a.y += v.y; a.z += v.z; a.w += v.w;
}

__global__ __launch_bounds__(THREADS, 16)
void segment_csr_kernel(const float* __restrict__ x,
                        const void* __restrict__ indptr_raw,
                        float* __restrict__ out) {
    const int lane = threadIdx.x & 31;
    const bool is32 = (g_indptr_is32 != 0);
    const float4* xr = reinterpret_cast<const float4*>(x) + lane;

    for (;;) {
        // One warp pops one segment id from the shared pool.
        unsigned int seg = 0u;
        if (lane == 0) seg = atomicAdd(&g_work, 1u);
        seg = __shfl_sync(0xFFFFFFFFu, seg, 0);
        if (seg >= N_SEG) break;

        int s, e;
        if (is32) {
            const int* p = (const int*)indptr_raw;
            s = p[seg]; e = p[seg + 1];
        } else {
            const long long* p = (const long long*)indptr_raw;
            s = (int)p[seg]; e = (int)p[seg + 1];
        }

        // lane l owns columns [4l,4l+4): each row is one fully-coalesced
        // 512B warp transaction. 4 independent LDG.128 in flight,
        // folded into 2 accumulators to keep regs <= 32.
        float4 a0 = make_float4(0.f, 0.f, 0.f, 0.f);
        float4 a1 = make_float4(0.f, 0.f, 0.f, 0.f);

        int r = s;
        for (; r + 4 <= e; r += 4) {
            const float4 v0 = __ldcs(xr + (size_t)(r    ) * 32);
            const float4 v1 = __ldcs(xr + (size_t)(r + 1) * 32);
            const float4 v2 = __ldcs(xr + (size_t)(r + 2) * 32);
            const float4 v3 = __ldcs(xr + (size_t)(r + 3) * 32);
            acc4(a0, v0); acc4(a1, v1); acc4(a0, v2); acc4(a1, v3);
        }
        for (; r < e; ++r) {
            acc4(a0, __ldcs(xr + (size_t)r * 32));
        }
        acc4(a0, a1);

        __stcs(reinterpret_cast<float4*>(out) + (size_t)seg * 32 + lane, a0);
    }
}

extern "C" void kernel_launch(void* const* d_in, const int* in_sizes, int n_in,
                              void* d_out, int out_size) {
    const float* x     = (const float*)d_in[0];
    const void* indptr = d_in[1];
    float* out         = (float*)d_out;

    init_kernel<<<1, 1>>>((const int*)indptr);
    segment_csr_kernel<<<GRID, THREADS>>>(x, indptr, out);
}

// round 5
// speedup vs baseline: 1.3238x; 1.3238x over previous
#include <cuda_runtime.h>

#define N_SEG   65536
#define TOTAL   2097152
#define D       128
#define THREADS 64
#define WARPS_PER_BLOCK (THREADS / 32)

// 1 -> indptr is int32, 0 -> indptr is int64
__device__ int g_indptr_is32;

__global__ void detect_dtype_kernel(const int* __restrict__ indptr32) {
    // Safe probe: word 65536 exists in both layouts.
    // int32 layout: indptr32[65536] == TOTAL (last element).
    // int64 layout: indptr32[65536] == high word of indptr[32768] == 0.
    g_indptr_is32 = (indptr32[N_SEG] == TOTAL) ? 1 : 0;
}

__device__ __forceinline__ void acc4(float4& a, const float4 v) {
    a.x += v.x; a.y += v.y; a.z += v.z; a.w += v.w;
}

__global__ __launch_bounds__(THREADS, 32)
void segment_csr_kernel(const float* __restrict__ x,
                        const void* __restrict__ indptr_raw,
                        float* __restrict__ out) {
    const int warp = (blockIdx.x * WARPS_PER_BLOCK) + (threadIdx.x >> 5);
    const int lane = threadIdx.x & 31;
    if (warp >= N_SEG) return;

    int s, e;
    if (g_indptr_is32) {
        const int* p = (const int*)indptr_raw;
        s = p[warp]; e = p[warp + 1];
    } else {
        const long long* p = (const long long*)indptr_raw;
        s = (int)p[warp]; e = (int)p[warp + 1];
    }

    // lane l owns columns [4l,4l+4): each row is one fully-coalesced 512B
    // warp transaction. 4 independent LDG.128 in flight per iteration,
    // folded into 2 accumulators to keep regs <= 32 (full occupancy).
    const float4* xr = reinterpret_cast<const float4*>(x) + lane;

    float4 a0 = make_float4(0.f, 0.f, 0.f, 0.f);
    float4 a1 = make_float4(0.f, 0.f, 0.f, 0.f);

    int r = s;
    for (; r + 4 <= e; r += 4) {
        const float4 v0 = __ldcs(xr + (size_t)(r    ) * 32);
        const float4 v1 = __ldcs(xr + (size_t)(r + 1) * 32);
        const float4 v2 = __ldcs(xr + (size_t)(r + 2) * 32);
        const float4 v3 = __ldcs(xr + (size_t)(r + 3) * 32);
        acc4(a0, v0); acc4(a1, v1); acc4(a0, v2); acc4(a1, v3);
    }
    for (; r < e; ++r) {
        acc4(a0, __ldcs(xr + (size_t)r * 32));
    }
    acc4(a0, a1);

    __stcs(reinterpret_cast<float4*>(out) + (size_t)warp * 32 + lane, a0);
}

extern "C" void kernel_launch(void* const* d_in, const int* in_sizes, int n_in,
                              void* d_out, int out_size) {
    const float* x     = (const float*)d_in[0];
    const void* indptr = d_in[1];
    float* out         = (float*)d_out;

    detect_dtype_kernel<<<1, 1>>>((const int*)indptr);

    const int blocks = (N_SEG + WARPS_PER_BLOCK - 1) / WARPS_PER_BLOCK;
    segment_csr_kernel<<<blocks, THREADS>>>(x, indptr, out);
}

// round 6
// speedup vs baseline: 1.4653x; 1.1069x over previous
#include <cuda_runtime.h>

#define N_SEG   65536
#define TOTAL   2097152
#define D       128

// 1 -> indptr is int32, 0 -> indptr is int64
__device__ int g_indptr_is32;

__global__ void detect_dtype_kernel(const int* __restrict__ indptr32) {
    // Safe probe: word 65536 exists in both layouts.
    // int32 layout: indptr32[65536] == TOTAL (last element).
    // int64 layout: indptr32[65536] == high word of indptr[32768] == 0.
    g_indptr_is32 = (indptr32[N_SEG] == TOTAL) ? 1 : 0;
}

__device__ __forceinline__ void acc4(float4& a, const float4 v) {
    a.x += v.x; a.y += v.y; a.z += v.z; a.w += v.w;
}

__global__ __launch_bounds__(32, 32)
void segment_csr_kernel(const float* __restrict__ x,
                        const void* __restrict__ indptr_raw,
                        float* __restrict__ out) {
    const int seg  = blockIdx.x;          // one warp == one CTA == one segment
    const int lane = threadIdx.x;

    int s, e;
    if (g_indptr_is32) {
        const int* p = (const int*)indptr_raw;
        s = p[seg]; e = p[seg + 1];
    } else {
        const long long* p = (const long long*)indptr_raw;
        s = (int)p[seg]; e = (int)p[seg + 1];
    }

    // lane l owns columns [4l,4l+4): each row is one fully-coalesced 512B
    // warp transaction. Software pipeline: prefetch rows r+4..r+7 while
    // accumulating rows r..r+3 -> ~8 LDG.128 in flight at the stall point.
    const float4* xr = reinterpret_cast<const float4*>(x) + lane;

    float4 a0 = make_float4(0.f, 0.f, 0.f, 0.f);
    float4 a1 = make_float4(0.f, 0.f, 0.f, 0.f);

    int r = s;
    if (r + 4 <= e) {
        float4 p0 = __ldcs(xr + (size_t)(r    ) * 32);
        float4 p1 = __ldcs(xr + (size_t)(r + 1) * 32);
        float4 p2 = __ldcs(xr + (size_t)(r + 2) * 32);
        float4 p3 = __ldcs(xr + (size_t)(r + 3) * 32);
        r += 4;
        for (; r + 4 <= e; r += 4) {
            const float4 q0 = __ldcs(xr + (size_t)(r    ) * 32);
            const float4 q1 = __ldcs(xr + (size_t)(r + 1) * 32);
            const float4 q2 = __ldcs(xr + (size_t)(r + 2) * 32);
            const float4 q3 = __ldcs(xr + (size_t)(r + 3) * 32);
            acc4(a0, p0); acc4(a1, p1); acc4(a0, p2); acc4(a1, p3);
            p0 = q0; p1 = q1; p2 = q2; p3 = q3;
        }
        acc4(a0, p0); acc4(a1, p1); acc4(a0, p2); acc4(a1, p3);
    }
    for (; r < e; ++r) {
        acc4(a0, __ldcs(xr + (size_t)r * 32));
    }
    acc4(a0, a1);

    __stcs(reinterpret_cast<float4*>(out) + (size_t)seg * 32 + lane, a0);
}

extern "C" void kernel_launch(void* const* d_in, const int* in_sizes, int n_in,
                              void* d_out, int out_size) {
    const float* x     = (const float*)d_in[0];
    const void* indptr = d_in[1];
    float* out         = (float*)d_out;

    detect_dtype_kernel<<<1, 1>>>((const int*)indptr);
    segment_csr_kernel<<<N_SEG, 32>>>(x, indptr, out);
}